// round 13
// baseline (speedup 1.0000x reference)
#include <cuda_runtime.h>
#include <cuda_fp16.h>
#include <math.h>

#define NMAX 100000
#define EMAX 1600000

// Scratch (device globals)
__device__ __align__(16) int                g_degi[NMAX];
__device__ __align__(16) int                g_start[NMAX + 1];
__device__ __align__(16) int                g_bsum[(NMAX + 255) / 256 + 1];
__device__ __align__(16) int                g_srcs[EMAX];
__device__ __align__(16) unsigned long long g_edge[EMAX];  // r:17 | c:17<<17 | rank<<34
__device__ __align__(16) float              g_dinv[NMAX];
__device__ __align__(16) float              g_xn[NMAX * 2];
__device__ __align__(16) __half             g_h2n[NMAX * 32];
__device__ __align__(16) __half             g_na[NMAX * 16];
__device__ __align__(16) __half             g_nb[NMAX * 16];
__device__ int g_i64;

// software grid barrier state (gen monotone across calls; count self-resets)
__device__ unsigned g_bar_count = 0;
__device__ volatile unsigned g_bar_gen = 0;

__device__ __forceinline__ void grid_barrier(int nb) {
    __syncthreads();
    if (threadIdx.x == 0) {
        __threadfence();
        unsigned gen = g_bar_gen;  // always equals the barrier index (see analysis)
        if (atomicAdd(&g_bar_count, 1u) == (unsigned)nb - 1u) {
            g_bar_count = 0;
            __threadfence();
            g_bar_gen = gen + 1u;
        } else {
            while (g_bar_gen == gen) { __nanosleep(64); }
        }
        __threadfence();
    }
    __syncthreads();
}

__device__ __forceinline__ void acc_slice(float* acc, uint4 raw) {
    const __half2* hh = reinterpret_cast<const __half2*>(&raw);
#pragma unroll
    for (int k = 0; k < 4; k++) {
        float2 f = __half22float2(hh[k]);
        acc[2 * k] += f.x; acc[2 * k + 1] += f.y;
    }
}

// ---------------------------------------------------------------------------
// One persistent kernel, 8 phases, 7 grid barriers.
__global__ void __launch_bounds__(256) k_fused(
    const float* __restrict__ x, const void* __restrict__ ei,
    const float* __restrict__ ea,
    const float* __restrict__ W1, const float* __restrict__ b1,
    const float* __restrict__ W2, const float* __restrict__ b2,
    const float* __restrict__ mW1, const float* __restrict__ mb1,
    const float* __restrict__ mW2, const float* __restrict__ mb2,
    float* __restrict__ out, int n, int e)
{
    const int nb = gridDim.x;
    const int t = threadIdx.x;
    const int gt0 = blockIdx.x * 256 + t;
    const int stride = nb * 256;
    const int lane = t & 31, wid = t >> 5;
    const int nchunk = (n + 255) >> 8;

    __shared__ float pool[3104];      // reused per phase
    __shared__ int ws[8];
    __shared__ int s_off;
    __shared__ int s_odd;

    // ---- phase 0: dtype probe + zero degi + start[n] ----
    if (blockIdx.x == 0) {
        if (t == 0) { s_odd = 0; g_start[n] = e; }
        __syncthreads();
        if (t < 128 && 2 * t + 1 < 2 * e) {
            if (reinterpret_cast<const unsigned*>(ei)[2 * t + 1] != 0u) s_odd = 1;
        }
        __syncthreads();
        if (t == 0) g_i64 = s_odd ? 0 : 1;
    }
    for (int i = gt0; i < n; i += stride) g_degi[i] = 0;
    grid_barrier(nb);

    // ---- phase 1: decode + histogram + pack ----
    {
        bool i64 = (g_i64 != 0);
        for (int i = gt0; i < e; i += stride) {
            unsigned r, c;
            if (i64) {
                r = (unsigned)(reinterpret_cast<const long long*>(ei)[i]);
                c = (unsigned)(reinterpret_cast<const long long*>(ei)[(size_t)e + i]);
            } else {
                r = (unsigned)reinterpret_cast<const int*>(ei)[i];
                c = (unsigned)reinterpret_cast<const int*>(ei)[(size_t)e + i];
            }
            unsigned rank = (unsigned)atomicAdd(&g_degi[c], 1);
            g_edge[i] = (unsigned long long)r | ((unsigned long long)c << 17)
                      | ((unsigned long long)rank << 34);
        }
    }
    grid_barrier(nb);

    // ---- phase 2: per-chunk sums ----
    for (int ch = blockIdx.x; ch < nchunk; ch += nb) {
        int i = ch * 256 + t;
        int v = (i < n) ? g_degi[i] : 0;
#pragma unroll
        for (int o = 16; o > 0; o >>= 1) v += __shfl_down_sync(0xFFFFFFFFu, v, o);
        if (lane == 0) ws[wid] = v;
        __syncthreads();
        if (t == 0) {
            int s = 0;
#pragma unroll
            for (int w = 0; w < 8; w++) s += ws[w];
            g_bsum[ch] = s;
        }
        __syncthreads();
    }
    grid_barrier(nb);

    // ---- phase 3: per-chunk offset reduce + local scan + dinv/xn ----
    for (int ch = blockIdx.x; ch < nchunk; ch += nb) {
        {
            int v = 0;
            if (t < ch) v += g_bsum[t];
            if (t + 256 < ch) v += g_bsum[t + 256];
#pragma unroll
            for (int o = 16; o > 0; o >>= 1) v += __shfl_down_sync(0xFFFFFFFFu, v, o);
            if (lane == 0) ws[wid] = v;
            __syncthreads();
            if (t == 0) {
                int s = 0;
#pragma unroll
                for (int w = 0; w < 8; w++) s += ws[w];
                s_off = s;
            }
            __syncthreads();
        }
        int i = ch * 256 + t;
        int v = (i < n) ? g_degi[i] : 0;
        int s = v;
#pragma unroll
        for (int o = 1; o < 32; o <<= 1) {
            int u = __shfl_up_sync(0xFFFFFFFFu, s, o);
            if (lane >= o) s += u;
        }
        if (lane == 31) ws[wid] = s;
        __syncthreads();
        if (wid == 0 && lane < 8) {
            int w = ws[lane];
#pragma unroll
            for (int o = 1; o < 8; o <<= 1) {
                int u = __shfl_up_sync(0x000000FFu, w, o);
                if (lane >= o) w += u;
            }
            ws[lane] = w;
        }
        __syncthreads();
        int excl = s_off + (wid ? ws[wid - 1] : 0) + s - v;
        if (i < n) {
            g_start[i] = excl;
            float di = rsqrtf((float)(v + 1));
            g_dinv[i] = di;
            float2 xv = reinterpret_cast<const float2*>(x)[i];
            reinterpret_cast<float2*>(g_xn)[i] = make_float2(di * xv.x, di * xv.y);
        }
        __syncthreads();
    }
    grid_barrier(nb);

    // ---- phase 4: scatter (atomic-free) ----
    for (int i = gt0; i < e; i += stride) {
        unsigned long long v = g_edge[i];
        int r = (int)(v & 0x1FFFFu);
        int c = (int)((v >> 17) & 0x1FFFFu);
        int rank = (int)(v >> 34);
        g_srcs[g_start[c] + rank] = r;
    }
    grid_barrier(nb);

    // ---- phase 5: layer 1 ----
    {
        float* sW1 = pool;            // 128
        float* sb1 = pool + 128;      // 64
        float* sW2 = pool + 192;      // 2048
        for (int i = t; i < 128; i += 256) sW1[i] = W1[i];
        for (int i = t; i < 64; i += 256) sb1[i] = b1[i];
        for (int i = t; i < 2048; i += 256) sW2[i] = W2[i];
        __syncthreads();

        for (int nn = gt0; nn < n; nn += stride) {
            int s0 = g_start[nn], s1 = g_start[nn + 1];
            float a0 = 0.0f, a1 = 0.0f;
            int j = s0;
            for (; j + 4 <= s1; j += 4) {
                int r0 = g_srcs[j], r1 = g_srcs[j + 1], r2 = g_srcs[j + 2], r3 = g_srcs[j + 3];
                float2 v0 = reinterpret_cast<const float2*>(g_xn)[r0];
                float2 v1 = reinterpret_cast<const float2*>(g_xn)[r1];
                float2 v2 = reinterpret_cast<const float2*>(g_xn)[r2];
                float2 v3 = reinterpret_cast<const float2*>(g_xn)[r3];
                a0 += (v0.x + v1.x) + (v2.x + v3.x);
                a1 += (v0.y + v1.y) + (v2.y + v3.y);
            }
            for (; j < s1; j++) {
                float2 v = reinterpret_cast<const float2*>(g_xn)[g_srcs[j]];
                a0 += v.x; a1 += v.y;
            }
            float di = g_dinv[nn];
            float2 xv = reinterpret_cast<const float2*>(g_xn)[nn];
            float v0 = di * (a0 + xv.x);
            float v1 = di * (a1 + xv.y);

            float acc[32];
#pragma unroll
            for (int k = 0; k < 32; k++) acc[k] = 0.0f;
#pragma unroll 4
            for (int jj = 0; jj < 64; jj++) {
                float h = fmaxf(fmaf(v0, sW1[jj], fmaf(v1, sW1[64 + jj], sb1[jj])), 0.0f);
#pragma unroll
                for (int k = 0; k < 32; k++) acc[k] = fmaf(h, sW2[jj * 32 + k], acc[k]);
            }

            __half2 hp[16];
#pragma unroll
            for (int k = 0; k < 16; k++)
                hp[k] = __floats2half2_rn(di * acc[2 * k], di * acc[2 * k + 1]);
            uint4* o = reinterpret_cast<uint4*>(g_h2n + (size_t)nn * 32);
            const uint4* src = reinterpret_cast<const uint4*>(hp);
#pragma unroll
            for (int k = 0; k < 4; k++) o[k] = src[k];
        }
    }
    grid_barrier(nb);

    // ---- phase 6: layer 2 (4 threads/node, 64-node tiles) ----
    {
        float* sAB = pool;            // 1024
        float* sb2 = pool + 1024;     // 32
        float* sh  = pool + 1056;     // 2048
        for (int idx = t; idx < 1024; idx += 256) {
            int k = idx >> 5, i = idx & 31;
            sAB[idx] = (i < 16) ? mW1[k * 16 + i] : mW1[(32 + k) * 16 + (i - 16)];
        }
        if (t < 32) sb2[t] = b2[t];
        __syncthreads();

        int local = t >> 2;
        int p = t & 3;
        int ntiles = (n + 63) >> 6;
        for (int tile = blockIdx.x; tile < ntiles; tile += nb) {
            int nn = tile * 64 + local;
            bool active = (nn < n);
            if (active) {
                int s0 = g_start[nn], s1 = g_start[nn + 1];
                float acc[8];
                {
                    uint4 raw = reinterpret_cast<const uint4*>(g_h2n + (size_t)nn * 32)[p];
                    const __half2* hh = reinterpret_cast<const __half2*>(&raw);
#pragma unroll
                    for (int k = 0; k < 4; k++) {
                        float2 f = __half22float2(hh[k]);
                        acc[2 * k] = f.x; acc[2 * k + 1] = f.y;
                    }
                }
                int j = s0;
                for (; j + 2 <= s1; j += 2) {
                    int r0 = g_srcs[j], r1 = g_srcs[j + 1];
                    uint4 w0 = reinterpret_cast<const uint4*>(g_h2n + (size_t)r0 * 32)[p];
                    uint4 w1 = reinterpret_cast<const uint4*>(g_h2n + (size_t)r1 * 32)[p];
                    acc_slice(acc, w0);
                    acc_slice(acc, w1);
                }
                if (j < s1) {
                    int r0 = g_srcs[j];
                    acc_slice(acc, reinterpret_cast<const uint4*>(g_h2n + (size_t)r0 * 32)[p]);
                }
                float di = g_dinv[nn];
#pragma unroll
                for (int k = 0; k < 8; k++)
                    sh[local * 32 + 8 * p + k] = fmaxf(fmaf(di, acc[k], sb2[8 * p + k]), 0.0f);
            }
            __syncthreads();
            if (active) {
                float o8[8];
#pragma unroll
                for (int i = 0; i < 8; i++) o8[i] = 0.0f;
                const float* hrow = sh + local * 32;
#pragma unroll 8
                for (int k = 0; k < 32; k++) {
                    float h = hrow[k];
                    const float* w = sAB + k * 32 + 8 * p;
#pragma unroll
                    for (int i = 0; i < 8; i++) o8[i] = fmaf(h, w[i], o8[i]);
                }
                __half2 hp[4];
#pragma unroll
                for (int k = 0; k < 4; k++)
                    hp[k] = __floats2half2_rn(o8[2 * k], o8[2 * k + 1]);
                __half* base = (p < 2) ? (g_na + (size_t)nn * 16 + 8 * p)
                                       : (g_nb + (size_t)nn * 16 + 8 * (p - 2));
                *reinterpret_cast<uint4*>(base) = *reinterpret_cast<const uint4*>(hp);
            }
            __syncthreads();
        }
    }
    grid_barrier(nb);

    // ---- phase 7: edge MLP ----
    {
        float* sw64 = pool;           // 16
        float* smb1 = pool + 16;      // 16
        float* smw2 = pool + 32;      // 16
        float* smb2 = pool + 48;      // 1
        if (t < 16) {
            sw64[t] = mW1[64 * 16 + t];
            smb1[t] = mb1[t];
            smw2[t] = mW2[t];
        }
        if (t == 0) smb2[0] = mb2[0];
        __syncthreads();

        for (int i = gt0; i < e; i += stride) {
            unsigned long long v = g_edge[i];
            int r = (int)(v & 0x1FFFFu);
            int c = (int)((v >> 17) & 0x1FFFFu);
            float attr = ea[i];

            const uint4* pa = reinterpret_cast<const uint4*>(g_na + (size_t)r * 16);
            const uint4* pb = reinterpret_cast<const uint4*>(g_nb + (size_t)c * 16);
            uint4 ra0 = pa[0], ra1 = pa[1];
            uint4 rb0 = pb[0], rb1 = pb[1];

            float s = 0.0f;
            const __half2* ha = reinterpret_cast<const __half2*>(&ra0);
            const __half2* hb = reinterpret_cast<const __half2*>(&rb0);
#pragma unroll
            for (int q = 0; q < 4; q++) {
                float2 av = __half22float2(ha[q]);
                float2 bv = __half22float2(hb[q]);
                float h;
                h = fmaxf(av.x + bv.x + fmaf(attr, sw64[2 * q], smb1[2 * q]), 0.0f);
                s = fmaf(h, smw2[2 * q], s);
                h = fmaxf(av.y + bv.y + fmaf(attr, sw64[2 * q + 1], smb1[2 * q + 1]), 0.0f);
                s = fmaf(h, smw2[2 * q + 1], s);
            }
            const __half2* ha1 = reinterpret_cast<const __half2*>(&ra1);
            const __half2* hb1 = reinterpret_cast<const __half2*>(&rb1);
#pragma unroll
            for (int q = 0; q < 4; q++) {
                float2 av = __half22float2(ha1[q]);
                float2 bv = __half22float2(hb1[q]);
                float h;
                h = fmaxf(av.x + bv.x + fmaf(attr, sw64[8 + 2 * q], smb1[8 + 2 * q]), 0.0f);
                s = fmaf(h, smw2[8 + 2 * q], s);
                h = fmaxf(av.y + bv.y + fmaf(attr, sw64[8 + 2 * q + 1], smb1[8 + 2 * q + 1]), 0.0f);
                s = fmaf(h, smw2[8 + 2 * q + 1], s);
            }
            float z = s + smb2[0];
            out[i] = 1.0f / (1.0f + __expf(-z));
        }
    }
}

// ---------------------------------------------------------------------------
extern "C" void kernel_launch(void* const* d_in, const int* in_sizes, int n_in,
                              void* d_out, int out_size) {
    const float* x = (const float*)d_in[0];
    const void* ei = d_in[1];
    const float* ea = (const float*)d_in[2];

    int base = (in_sizes[3] == 128) ? 3 : 4;
    const float* W1 = (const float*)d_in[base + 0];
    const float* b1 = (const float*)d_in[base + 1];
    const float* W2 = (const float*)d_in[base + 2];
    const float* b2 = (const float*)d_in[base + 3];
    const float* mW1 = (const float*)d_in[base + 4];
    const float* mb1 = (const float*)d_in[base + 5];
    const float* mW2 = (const float*)d_in[base + 6];
    const float* mb2 = (const float*)d_in[base + 7];

    int n = in_sizes[0] / 2;
    int e = in_sizes[1] / 2;
    float* out = (float*)d_out;

    // co-residency-guaranteed persistent grid
    int dev = 0;
    cudaGetDevice(&dev);
    int sms = 0;
    cudaDeviceGetAttribute(&sms, cudaDevAttrMultiProcessorCount, dev);
    int bpm = 0;
    cudaOccupancyMaxActiveBlocksPerMultiprocessor(&bpm, (const void*)k_fused, 256, 0);
    if (bpm < 1) bpm = 1;
    int grid = sms * bpm;

    k_fused<<<grid, 256>>>(x, ei, ea, W1, b1, W2, b2,
                           mW1, mb1, mW2, mb2, out, n, e);
}

// round 14
// speedup vs baseline: 1.0735x; 1.0735x over previous
#include <cuda_runtime.h>
#include <cuda_fp16.h>
#include <math.h>

#define NMAX 100000
#define EMAX 1600000

// Scratch (device globals)
__device__ __align__(16) int                g_degi[NMAX];
__device__ __align__(16) int                g_start[NMAX + 1];
__device__ __align__(16) int                g_bsum[(NMAX + 255) / 256 + 1];
__device__ __align__(16) int                g_srcs[EMAX];
__device__ __align__(16) unsigned long long g_edge[EMAX];  // r:17 | c:17<<17 | rank<<34
__device__ __align__(16) float              g_dinv[NMAX];
__device__ __align__(16) float              g_xn[NMAX * 2];
__device__ __align__(16) __half             g_h2n[NMAX * 32];
__device__ __align__(16) __half             g_na[NMAX * 16];
__device__ __align__(16) __half             g_nb[NMAX * 16];
__device__ int g_i64;

// software grid barrier (gen monotone across graph replays; count self-resets)
__device__ unsigned g_bar_count = 0;
__device__ volatile unsigned g_bar_gen = 0;

__device__ __forceinline__ void grid_barrier(int nb) {
    __syncthreads();
    if (threadIdx.x == 0) {
        __threadfence();
        unsigned gen = g_bar_gen;
        if (atomicAdd(&g_bar_count, 1u) == (unsigned)nb - 1u) {
            g_bar_count = 0;
            __threadfence();
            g_bar_gen = gen + 1u;
        } else {
            while (g_bar_gen == gen) { __nanosleep(64); }
        }
        __threadfence();
    }
    __syncthreads();
}

// ---------------------------------------------------------------------------
// Persistent CSR-build kernel: probe+zero, decode+histogram, chunk sums,
// offsets+scan+dinv/xn, scatter. All phases low-register -> full occupancy.
__global__ void __launch_bounds__(256) k_build(
    const float* __restrict__ x, const void* __restrict__ ei, int n, int e)
{
    const int nb = gridDim.x;
    const int t = threadIdx.x;
    const int gt0 = blockIdx.x * 256 + t;
    const int stride = nb * 256;
    const int lane = t & 31, wid = t >> 5;
    const int nchunk = (n + 255) >> 8;

    __shared__ int ws[8];
    __shared__ int s_off;
    __shared__ int s_odd;

    // ---- phase 0: dtype probe + zero degi + start[n] ----
    if (blockIdx.x == 0) {
        if (t == 0) { s_odd = 0; g_start[n] = e; }
        __syncthreads();
        if (t < 128 && 2 * t + 1 < 2 * e) {
            if (reinterpret_cast<const unsigned*>(ei)[2 * t + 1] != 0u) s_odd = 1;
        }
        __syncthreads();
        if (t == 0) g_i64 = s_odd ? 0 : 1;
    }
    for (int i = gt0; i < n; i += stride) g_degi[i] = 0;
    grid_barrier(nb);

    // ---- phase 1: decode + histogram + pack ----
    {
        bool i64 = (g_i64 != 0);
        for (int i = gt0; i < e; i += stride) {
            unsigned r, c;
            if (i64) {
                r = (unsigned)(reinterpret_cast<const long long*>(ei)[i]);
                c = (unsigned)(reinterpret_cast<const long long*>(ei)[(size_t)e + i]);
            } else {
                r = (unsigned)reinterpret_cast<const int*>(ei)[i];
                c = (unsigned)reinterpret_cast<const int*>(ei)[(size_t)e + i];
            }
            unsigned rank = (unsigned)atomicAdd(&g_degi[c], 1);
            g_edge[i] = (unsigned long long)r | ((unsigned long long)c << 17)
                      | ((unsigned long long)rank << 34);
        }
    }
    grid_barrier(nb);

    // ---- phase 2: per-chunk sums ----
    for (int ch = blockIdx.x; ch < nchunk; ch += nb) {
        int i = ch * 256 + t;
        int v = (i < n) ? g_degi[i] : 0;
#pragma unroll
        for (int o = 16; o > 0; o >>= 1) v += __shfl_down_sync(0xFFFFFFFFu, v, o);
        if (lane == 0) ws[wid] = v;
        __syncthreads();
        if (t == 0) {
            int s = 0;
#pragma unroll
            for (int w = 0; w < 8; w++) s += ws[w];
            g_bsum[ch] = s;
        }
        __syncthreads();
    }
    grid_barrier(nb);

    // ---- phase 3: per-chunk offset reduce + local scan + dinv/xn ----
    for (int ch = blockIdx.x; ch < nchunk; ch += nb) {
        {
            int v = 0;
            if (t < ch) v += g_bsum[t];
            if (t + 256 < ch) v += g_bsum[t + 256];
#pragma unroll
            for (int o = 16; o > 0; o >>= 1) v += __shfl_down_sync(0xFFFFFFFFu, v, o);
            if (lane == 0) ws[wid] = v;
            __syncthreads();
            if (t == 0) {
                int s = 0;
#pragma unroll
                for (int w = 0; w < 8; w++) s += ws[w];
                s_off = s;
            }
            __syncthreads();
        }
        int i = ch * 256 + t;
        int v = (i < n) ? g_degi[i] : 0;
        int s = v;
#pragma unroll
        for (int o = 1; o < 32; o <<= 1) {
            int u = __shfl_up_sync(0xFFFFFFFFu, s, o);
            if (lane >= o) s += u;
        }
        if (lane == 31) ws[wid] = s;
        __syncthreads();
        if (wid == 0 && lane < 8) {
            int w = ws[lane];
#pragma unroll
            for (int o = 1; o < 8; o <<= 1) {
                int u = __shfl_up_sync(0x000000FFu, w, o);
                if (lane >= o) w += u;
            }
            ws[lane] = w;
        }
        __syncthreads();
        int excl = s_off + (wid ? ws[wid - 1] : 0) + s - v;
        if (i < n) {
            g_start[i] = excl;
            float di = rsqrtf((float)(v + 1));
            g_dinv[i] = di;
            float2 xv = reinterpret_cast<const float2*>(x)[i];
            reinterpret_cast<float2*>(g_xn)[i] = make_float2(di * xv.x, di * xv.y);
        }
        __syncthreads();
    }
    grid_barrier(nb);

    // ---- phase 4: scatter (atomic-free) ----
    for (int i = gt0; i < e; i += stride) {
        unsigned long long v = g_edge[i];
        int r = (int)(v & 0x1FFFFu);
        int c = (int)((v >> 17) & 0x1FFFFu);
        int rank = (int)(v >> 34);
        g_srcs[g_start[c] + rank] = r;
    }
}

// ---------------------------------------------------------------------------
// layer 1 fused: gather xn (unroll-4), GEMV, write fp16 h2n
__global__ void k_layer1(const float* __restrict__ W1,  // [2,64]
                         const float* __restrict__ b1,  // [64]
                         const float* __restrict__ W2,  // [64,32]
                         int n) {
    __shared__ float sW1[128];
    __shared__ float sb1[64];
    __shared__ float sW2[2048];
    int t = threadIdx.x;
    for (int i = t; i < 128; i += blockDim.x) sW1[i] = W1[i];
    for (int i = t; i < 64; i += blockDim.x) sb1[i] = b1[i];
    for (int i = t; i < 2048; i += blockDim.x) sW2[i] = W2[i];
    __syncthreads();

    int nn = blockIdx.x * blockDim.x + t;
    if (nn >= n) return;
    int s0 = g_start[nn], s1 = g_start[nn + 1];
    float a0 = 0.0f, a1 = 0.0f;
    int j = s0;
    for (; j + 4 <= s1; j += 4) {
        int r0 = g_srcs[j], r1 = g_srcs[j + 1], r2 = g_srcs[j + 2], r3 = g_srcs[j + 3];
        float2 v0 = reinterpret_cast<const float2*>(g_xn)[r0];
        float2 v1 = reinterpret_cast<const float2*>(g_xn)[r1];
        float2 v2 = reinterpret_cast<const float2*>(g_xn)[r2];
        float2 v3 = reinterpret_cast<const float2*>(g_xn)[r3];
        a0 += (v0.x + v1.x) + (v2.x + v3.x);
        a1 += (v0.y + v1.y) + (v2.y + v3.y);
    }
    for (; j < s1; j++) {
        float2 v = reinterpret_cast<const float2*>(g_xn)[g_srcs[j]];
        a0 += v.x; a1 += v.y;
    }
    float di = g_dinv[nn];
    float2 xv = reinterpret_cast<const float2*>(g_xn)[nn];
    float v0 = di * (a0 + xv.x);
    float v1 = di * (a1 + xv.y);

    float acc[32];
#pragma unroll
    for (int k = 0; k < 32; k++) acc[k] = 0.0f;
#pragma unroll 4
    for (int jj = 0; jj < 64; jj++) {
        float h = fmaxf(fmaf(v0, sW1[jj], fmaf(v1, sW1[64 + jj], sb1[jj])), 0.0f);
#pragma unroll
        for (int k = 0; k < 32; k++) acc[k] = fmaf(h, sW2[jj * 32 + k], acc[k]);
    }

    __half2 hp[16];
#pragma unroll
    for (int k = 0; k < 16; k++)
        hp[k] = __floats2half2_rn(di * acc[2 * k], di * acc[2 * k + 1]);
    uint4* o = reinterpret_cast<uint4*>(g_h2n + (size_t)nn * 32);
    const uint4* src = reinterpret_cast<const uint4*>(hp);
#pragma unroll
    for (int k = 0; k < 4; k++) o[k] = src[k];
}

__device__ __forceinline__ void acc_slice(float* acc, uint4 raw) {
    const __half2* hh = reinterpret_cast<const __half2*>(&raw);
#pragma unroll
    for (int k = 0; k < 4; k++) {
        float2 f = __half22float2(hh[k]);
        acc[2 * k] += f.x; acc[2 * k + 1] += f.y;
    }
}

// layer 2 fused, 4 threads/node, gather unroll-2
__global__ void k_layer2(const float* __restrict__ mW1,  // [65,16]
                         const float* __restrict__ b2,   // [32]
                         int n) {
    __shared__ float sAB[1024];
    __shared__ float sb2[32];
    __shared__ float sh[64 * 32];
    int t = threadIdx.x;
    for (int idx = t; idx < 1024; idx += blockDim.x) {
        int k = idx >> 5, i = idx & 31;
        sAB[idx] = (i < 16) ? mW1[k * 16 + i] : mW1[(32 + k) * 16 + (i - 16)];
    }
    for (int i = t; i < 32; i += blockDim.x) sb2[i] = b2[i];
    __syncthreads();

    int local = t >> 2;
    int p = t & 3;
    int nn = blockIdx.x * 64 + local;
    bool active = (nn < n);

    if (active) {
        int s0 = g_start[nn], s1 = g_start[nn + 1];
        float acc[8];
        {
            uint4 raw = reinterpret_cast<const uint4*>(g_h2n + (size_t)nn * 32)[p];
            const __half2* hh = reinterpret_cast<const __half2*>(&raw);
#pragma unroll
            for (int k = 0; k < 4; k++) {
                float2 f = __half22float2(hh[k]);
                acc[2 * k] = f.x; acc[2 * k + 1] = f.y;
            }
        }
        int j = s0;
        for (; j + 2 <= s1; j += 2) {
            int r0 = g_srcs[j], r1 = g_srcs[j + 1];
            uint4 w0 = reinterpret_cast<const uint4*>(g_h2n + (size_t)r0 * 32)[p];
            uint4 w1 = reinterpret_cast<const uint4*>(g_h2n + (size_t)r1 * 32)[p];
            acc_slice(acc, w0);
            acc_slice(acc, w1);
        }
        if (j < s1) {
            int r0 = g_srcs[j];
            acc_slice(acc, reinterpret_cast<const uint4*>(g_h2n + (size_t)r0 * 32)[p]);
        }
        float di = g_dinv[nn];
#pragma unroll
        for (int k = 0; k < 8; k++)
            sh[local * 32 + 8 * p + k] = fmaxf(fmaf(di, acc[k], sb2[8 * p + k]), 0.0f);
    }
    __syncthreads();

    if (active) {
        float o8[8];
#pragma unroll
        for (int i = 0; i < 8; i++) o8[i] = 0.0f;
        const float* hrow = sh + local * 32;
#pragma unroll 8
        for (int k = 0; k < 32; k++) {
            float h = hrow[k];
            const float* w = sAB + k * 32 + 8 * p;
#pragma unroll
            for (int i = 0; i < 8; i++) o8[i] = fmaf(h, w[i], o8[i]);
        }
        __half2 hp[4];
#pragma unroll
        for (int k = 0; k < 4; k++)
            hp[k] = __floats2half2_rn(o8[2 * k], o8[2 * k + 1]);
        __half* base = (p < 2) ? (g_na + (size_t)nn * 16 + 8 * p)
                               : (g_nb + (size_t)nn * 16 + 8 * (p - 2));
        *reinterpret_cast<uint4*>(base) = *reinterpret_cast<const uint4*>(hp);
    }
}

// per edge: hid = relu(na[r] + nb[c] + attr*mW1[64] + mb1); out = sigmoid(hid@mW2 + mb2)
__global__ void k_edge(const float* __restrict__ ea,
                       const float* __restrict__ mW1,
                       const float* __restrict__ mb1,
                       const float* __restrict__ mW2,
                       const float* __restrict__ mb2,
                       float* __restrict__ out, int e) {
    __shared__ float sw64[16], smb1[16], smw2[16];
    __shared__ float smb2;
    int t = threadIdx.x;
    if (t < 16) {
        sw64[t] = mW1[64 * 16 + t];
        smb1[t] = mb1[t];
        smw2[t] = mW2[t];
    }
    if (t == 0) smb2 = mb2[0];
    __syncthreads();

    int i = blockIdx.x * blockDim.x + t;
    if (i >= e) return;
    unsigned long long v = g_edge[i];
    int r = (int)(v & 0x1FFFFu);
    int c = (int)((v >> 17) & 0x1FFFFu);
    float attr = ea[i];

    const uint4* pa = reinterpret_cast<const uint4*>(g_na + (size_t)r * 16);
    const uint4* pb = reinterpret_cast<const uint4*>(g_nb + (size_t)c * 16);
    uint4 ra0 = pa[0], ra1 = pa[1];
    uint4 rb0 = pb[0], rb1 = pb[1];

    float s = 0.0f;
    const __half2* ha = reinterpret_cast<const __half2*>(&ra0);
    const __half2* hb = reinterpret_cast<const __half2*>(&rb0);
#pragma unroll
    for (int q = 0; q < 4; q++) {
        float2 av = __half22float2(ha[q]);
        float2 bv = __half22float2(hb[q]);
        float h;
        h = fmaxf(av.x + bv.x + fmaf(attr, sw64[2 * q], smb1[2 * q]), 0.0f);
        s = fmaf(h, smw2[2 * q], s);
        h = fmaxf(av.y + bv.y + fmaf(attr, sw64[2 * q + 1], smb1[2 * q + 1]), 0.0f);
        s = fmaf(h, smw2[2 * q + 1], s);
    }
    const __half2* ha1 = reinterpret_cast<const __half2*>(&ra1);
    const __half2* hb1 = reinterpret_cast<const __half2*>(&rb1);
#pragma unroll
    for (int q = 0; q < 4; q++) {
        float2 av = __half22float2(ha1[q]);
        float2 bv = __half22float2(hb1[q]);
        float h;
        h = fmaxf(av.x + bv.x + fmaf(attr, sw64[8 + 2 * q], smb1[8 + 2 * q]), 0.0f);
        s = fmaf(h, smw2[8 + 2 * q], s);
        h = fmaxf(av.y + bv.y + fmaf(attr, sw64[8 + 2 * q + 1], smb1[8 + 2 * q + 1]), 0.0f);
        s = fmaf(h, smw2[8 + 2 * q + 1], s);
    }
    float z = s + smb2;
    out[i] = 1.0f / (1.0f + __expf(-z));
}

// ---------------------------------------------------------------------------
extern "C" void kernel_launch(void* const* d_in, const int* in_sizes, int n_in,
                              void* d_out, int out_size) {
    const float* x = (const float*)d_in[0];
    const void* ei = d_in[1];
    const float* ea = (const float*)d_in[2];

    int base = (in_sizes[3] == 128) ? 3 : 4;
    const float* W1 = (const float*)d_in[base + 0];
    const float* b1 = (const float*)d_in[base + 1];
    const float* W2 = (const float*)d_in[base + 2];
    const float* b2 = (const float*)d_in[base + 3];
    const float* mW1 = (const float*)d_in[base + 4];
    const float* mb1 = (const float*)d_in[base + 5];
    const float* mW2 = (const float*)d_in[base + 6];
    const float* mb2 = (const float*)d_in[base + 7];

    int n = in_sizes[0] / 2;
    int e = in_sizes[1] / 2;
    float* out = (float*)d_out;

    const int B = 256;
    int gn = (n + B - 1) / B;
    int ge = (e + B - 1) / B;
    int gn4 = (n + 63) / 64;

    // co-residency-guaranteed persistent grid for the build kernel
    int dev = 0;
    cudaGetDevice(&dev);
    int sms = 0;
    cudaDeviceGetAttribute(&sms, cudaDevAttrMultiProcessorCount, dev);
    int bpm = 0;
    cudaOccupancyMaxActiveBlocksPerMultiprocessor(&bpm, (const void*)k_build, B, 0);
    if (bpm < 1) bpm = 1;
    int gb = sms * bpm;
    if (gb > ge) gb = ge;

    k_build<<<gb, B>>>(x, ei, n, e);
    k_layer1<<<gn, B>>>(W1, b1, W2, n);
    k_layer2<<<gn4, B>>>(mW1, b2, n);
    k_edge<<<ge, B>>>(ea, mW1, mb1, mW2, mb2, out, e);
}

// round 15
// speedup vs baseline: 1.1682x; 1.0882x over previous
#include <cuda_runtime.h>
#include <cuda_fp16.h>
#include <math.h>

#define NMAX 100000
#define EMAX 1600000
#define NBLK ((NMAX + 255) / 256)   // 391

// Scratch (device globals)
__device__ __align__(16) int                g_degi[NMAX];
__device__ __align__(16) int                g_start[NMAX + 1];
__device__ __align__(16) int                g_bsum[NBLK + 1];
__device__ __align__(16) int                g_srcs[EMAX];
__device__ __align__(16) unsigned long long g_edge[EMAX];  // r:17 | c:17<<17 | rank<<34
__device__ __align__(16) float              g_dinv[NMAX];
__device__ __align__(16) float              g_xn[NMAX * 2];
__device__ __align__(16) __half             g_h2n[NMAX * 32];
__device__ __align__(16) __half             g_na[NMAX * 16];
__device__ __align__(16) __half             g_nb[NMAX * 16];
__device__ int g_i64;

// ---------------------------------------------------------------------------
__global__ void k_init(const unsigned* __restrict__ ei_raw, int e, int n) {
    if (blockIdx.x == 0) {
        __shared__ int odd_nonzero;
        if (threadIdx.x == 0) odd_nonzero = 0;
        __syncthreads();
        int i = threadIdx.x;
        if (2 * i + 1 < 2 * e) {
            if (ei_raw[2 * i + 1] != 0u) odd_nonzero = 1;
        }
        __syncthreads();
        if (threadIdx.x == 0) {
            g_i64 = odd_nonzero ? 0 : 1;
            g_start[n] = e;            // total degree (excl self) is just e
        }
    }
    int i = blockIdx.x * blockDim.x + threadIdx.x;
    if (i < n) g_degi[i] = 0;
}

// decode edge_index; histogram in-degree; pack (r, c, rank) into u64.
__global__ void k_prep(const void* __restrict__ ei, int e) {
    int i = blockIdx.x * blockDim.x + threadIdx.x;
    if (i >= e) return;
    unsigned r, c;
    if (g_i64) {
        r = (unsigned)(reinterpret_cast<const long long*>(ei)[i]);
        c = (unsigned)(reinterpret_cast<const long long*>(ei)[(size_t)e + i]);
    } else {
        r = (unsigned)reinterpret_cast<const int*>(ei)[i];
        c = (unsigned)reinterpret_cast<const int*>(ei)[(size_t)e + i];
    }
    unsigned rank = (unsigned)atomicAdd(&g_degi[c], 1);
    g_edge[i] = (unsigned long long)r | ((unsigned long long)c << 17)
              | ((unsigned long long)rank << 34);
}

// scan phase 1: per-block sums of degi
__global__ void k_scan1(int n) {
    __shared__ int ws[8];
    int lane = threadIdx.x & 31, wid = threadIdx.x >> 5;
    int i = blockIdx.x * 256 + threadIdx.x;
    int v = (i < n) ? g_degi[i] : 0;
#pragma unroll
    for (int o = 16; o > 0; o >>= 1) v += __shfl_down_sync(0xFFFFFFFFu, v, o);
    if (lane == 0) ws[wid] = v;
    __syncthreads();
    if (threadIdx.x == 0) {
        int s = 0;
#pragma unroll
        for (int w = 0; w < 8; w++) s += ws[w];
        g_bsum[blockIdx.x] = s;
    }
}

// scan phase 2+3 fused: each block reduces bsum[0..b) for its own offset,
// then local exclusive scan; writes start, dinv, xn.
__global__ void k_scan(const float* __restrict__ x, int n) {
    __shared__ int ws[8];
    __shared__ int s_boff;
    int t = threadIdx.x;
    int lane = t & 31, wid = t >> 5;
    int b = blockIdx.x;

    {
        int v = 0;
        if (t < b) v += g_bsum[t];
        if (t + 256 < b) v += g_bsum[t + 256];
#pragma unroll
        for (int o = 16; o > 0; o >>= 1) v += __shfl_down_sync(0xFFFFFFFFu, v, o);
        if (lane == 0) ws[wid] = v;
        __syncthreads();
        if (t == 0) {
            int s = 0;
#pragma unroll
            for (int w = 0; w < 8; w++) s += ws[w];
            s_boff = s;
        }
        __syncthreads();
    }

    int i = b * 256 + t;
    int v = (i < n) ? g_degi[i] : 0;
    int s = v;
#pragma unroll
    for (int o = 1; o < 32; o <<= 1) {
        int u = __shfl_up_sync(0xFFFFFFFFu, s, o);
        if (lane >= o) s += u;
    }
    if (lane == 31) ws[wid] = s;
    __syncthreads();
    if (wid == 0 && lane < 8) {
        int w = ws[lane];
#pragma unroll
        for (int o = 1; o < 8; o <<= 1) {
            int u = __shfl_up_sync(0x000000FFu, w, o);
            if (lane >= o) w += u;
        }
        ws[lane] = w;
    }
    __syncthreads();
    int excl = s_boff + (wid ? ws[wid - 1] : 0) + s - v;
    if (i < n) {
        g_start[i] = excl;
        float di = rsqrtf((float)(v + 1));
        g_dinv[i] = di;
        float2 xv = reinterpret_cast<const float2*>(x)[i];
        reinterpret_cast<float2*>(g_xn)[i] = make_float2(di * xv.x, di * xv.y);
    }
}

// scatter edges into CSR slots — atomic-free
__global__ void k_scatter(int e) {
    int i = blockIdx.x * blockDim.x + threadIdx.x;
    if (i >= e) return;
    unsigned long long v = g_edge[i];
    int r = (int)(v & 0x1FFFFu);
    int c = (int)((v >> 17) & 0x1FFFFu);
    int rank = (int)(v >> 34);
    g_srcs[g_start[c] + rank] = r;
}

// layer 1 fused: gather xn (unroll-4), GEMV, write fp16 h2n
__global__ void k_layer1(const float* __restrict__ W1,  // [2,64]
                         const float* __restrict__ b1,  // [64]
                         const float* __restrict__ W2,  // [64,32]
                         int n) {
    __shared__ float sW1[128];
    __shared__ float sb1[64];
    __shared__ float sW2[2048];
    int t = threadIdx.x;
    for (int i = t; i < 128; i += blockDim.x) sW1[i] = W1[i];
    for (int i = t; i < 64; i += blockDim.x) sb1[i] = b1[i];
    for (int i = t; i < 2048; i += blockDim.x) sW2[i] = W2[i];
    __syncthreads();

    int nn = blockIdx.x * blockDim.x + t;
    if (nn >= n) return;
    int s0 = g_start[nn], s1 = g_start[nn + 1];
    float a0 = 0.0f, a1 = 0.0f;
    int j = s0;
    for (; j + 4 <= s1; j += 4) {
        int r0 = g_srcs[j], r1 = g_srcs[j + 1], r2 = g_srcs[j + 2], r3 = g_srcs[j + 3];
        float2 v0 = reinterpret_cast<const float2*>(g_xn)[r0];
        float2 v1 = reinterpret_cast<const float2*>(g_xn)[r1];
        float2 v2 = reinterpret_cast<const float2*>(g_xn)[r2];
        float2 v3 = reinterpret_cast<const float2*>(g_xn)[r3];
        a0 += (v0.x + v1.x) + (v2.x + v3.x);
        a1 += (v0.y + v1.y) + (v2.y + v3.y);
    }
    for (; j < s1; j++) {
        float2 v = reinterpret_cast<const float2*>(g_xn)[g_srcs[j]];
        a0 += v.x; a1 += v.y;
    }
    float di = g_dinv[nn];
    float2 xv = reinterpret_cast<const float2*>(g_xn)[nn];
    float v0 = di * (a0 + xv.x);
    float v1 = di * (a1 + xv.y);

    float acc[32];
#pragma unroll
    for (int k = 0; k < 32; k++) acc[k] = 0.0f;
#pragma unroll 4
    for (int jj = 0; jj < 64; jj++) {
        float h = fmaxf(fmaf(v0, sW1[jj], fmaf(v1, sW1[64 + jj], sb1[jj])), 0.0f);
#pragma unroll
        for (int k = 0; k < 32; k++) acc[k] = fmaf(h, sW2[jj * 32 + k], acc[k]);
    }

    __half2 hp[16];
#pragma unroll
    for (int k = 0; k < 16; k++)
        hp[k] = __floats2half2_rn(di * acc[2 * k], di * acc[2 * k + 1]);
    uint4* o = reinterpret_cast<uint4*>(g_h2n + (size_t)nn * 32);
    const uint4* src = reinterpret_cast<const uint4*>(hp);
#pragma unroll
    for (int k = 0; k < 4; k++) o[k] = src[k];
}

__device__ __forceinline__ void acc_slice(float* acc, uint4 raw) {
    const __half2* hh = reinterpret_cast<const __half2*>(&raw);
#pragma unroll
    for (int k = 0; k < 4; k++) {
        float2 f = __half22float2(hh[k]);
        acc[2 * k] += f.x; acc[2 * k + 1] += f.y;
    }
}

// layer 2 fused, 4 threads/node, gather unroll-2
__global__ void k_layer2(const float* __restrict__ mW1,  // [65,16]
                         const float* __restrict__ b2,   // [32]
                         int n) {
    __shared__ float sAB[1024];
    __shared__ float sb2[32];
    __shared__ float sh[64 * 32];
    int t = threadIdx.x;
    for (int idx = t; idx < 1024; idx += blockDim.x) {
        int k = idx >> 5, i = idx & 31;
        sAB[idx] = (i < 16) ? mW1[k * 16 + i] : mW1[(32 + k) * 16 + (i - 16)];
    }
    for (int i = t; i < 32; i += blockDim.x) sb2[i] = b2[i];
    __syncthreads();

    int local = t >> 2;
    int p = t & 3;
    int nn = blockIdx.x * 64 + local;
    bool active = (nn < n);

    if (active) {
        int s0 = g_start[nn], s1 = g_start[nn + 1];
        float acc[8];
        {
            uint4 raw = reinterpret_cast<const uint4*>(g_h2n + (size_t)nn * 32)[p];
            const __half2* hh = reinterpret_cast<const __half2*>(&raw);
#pragma unroll
            for (int k = 0; k < 4; k++) {
                float2 f = __half22float2(hh[k]);
                acc[2 * k] = f.x; acc[2 * k + 1] = f.y;
            }
        }
        int j = s0;
        for (; j + 2 <= s1; j += 2) {
            int r0 = g_srcs[j], r1 = g_srcs[j + 1];
            uint4 w0 = reinterpret_cast<const uint4*>(g_h2n + (size_t)r0 * 32)[p];
            uint4 w1 = reinterpret_cast<const uint4*>(g_h2n + (size_t)r1 * 32)[p];
            acc_slice(acc, w0);
            acc_slice(acc, w1);
        }
        if (j < s1) {
            int r0 = g_srcs[j];
            acc_slice(acc, reinterpret_cast<const uint4*>(g_h2n + (size_t)r0 * 32)[p]);
        }
        float di = g_dinv[nn];
#pragma unroll
        for (int k = 0; k < 8; k++)
            sh[local * 32 + 8 * p + k] = fmaxf(fmaf(di, acc[k], sb2[8 * p + k]), 0.0f);
    }
    __syncthreads();

    if (active) {
        float o8[8];
#pragma unroll
        for (int i = 0; i < 8; i++) o8[i] = 0.0f;
        const float* hrow = sh + local * 32;
#pragma unroll 8
        for (int k = 0; k < 32; k++) {
            float h = hrow[k];
            const float* w = sAB + k * 32 + 8 * p;
#pragma unroll
            for (int i = 0; i < 8; i++) o8[i] = fmaf(h, w[i], o8[i]);
        }
        __half2 hp[4];
#pragma unroll
        for (int k = 0; k < 4; k++)
            hp[k] = __floats2half2_rn(o8[2 * k], o8[2 * k + 1]);
        __half* base = (p < 2) ? (g_na + (size_t)nn * 16 + 8 * p)
                               : (g_nb + (size_t)nn * 16 + 8 * (p - 2));
        *reinterpret_cast<uint4*>(base) = *reinterpret_cast<const uint4*>(hp);
    }
}

// per edge, 2 threads/edge: lane p loads 16B slice p of na[r] and nb[c]
// (pair hits the same 128B line -> half the L1tex wavefronts), computes
// 8 hidden units, shfl-combines, lane 0 writes sigmoid.
__global__ void k_edge(const float* __restrict__ ea,
                       const float* __restrict__ mW1,
                       const float* __restrict__ mb1,
                       const float* __restrict__ mW2,
                       const float* __restrict__ mb2,
                       float* __restrict__ out, int e) {
    __shared__ float sw64[16], smb1[16], smw2[16];
    __shared__ float smb2;
    int t = threadIdx.x;
    if (t < 16) {
        sw64[t] = mW1[64 * 16 + t];
        smb1[t] = mb1[t];
        smw2[t] = mW2[t];
    }
    if (t == 0) smb2 = mb2[0];
    __syncthreads();

    int i = blockIdx.x * 128 + (t >> 1);   // edge index
    int p = t & 1;                          // slice
    if (i >= e) return;
    unsigned long long v = g_edge[i];
    int r = (int)(v & 0x1FFFFu);
    int c = (int)((v >> 17) & 0x1FFFFu);
    float attr = ea[i];

    uint4 ra = reinterpret_cast<const uint4*>(g_na + (size_t)r * 16)[p];
    uint4 rb = reinterpret_cast<const uint4*>(g_nb + (size_t)c * 16)[p];
    const __half2* ha = reinterpret_cast<const __half2*>(&ra);
    const __half2* hb = reinterpret_cast<const __half2*>(&rb);

    int k0 = 8 * p;
    float s = 0.0f;
#pragma unroll
    for (int q = 0; q < 4; q++) {
        float2 av = __half22float2(ha[q]);
        float2 bv = __half22float2(hb[q]);
        float h;
        h = fmaxf(av.x + bv.x + fmaf(attr, sw64[k0 + 2 * q], smb1[k0 + 2 * q]), 0.0f);
        s = fmaf(h, smw2[k0 + 2 * q], s);
        h = fmaxf(av.y + bv.y + fmaf(attr, sw64[k0 + 2 * q + 1], smb1[k0 + 2 * q + 1]), 0.0f);
        s = fmaf(h, smw2[k0 + 2 * q + 1], s);
    }
    s += __shfl_xor_sync(0xFFFFFFFFu, s, 1);
    if (p == 0) {
        float z = s + smb2;
        out[i] = 1.0f / (1.0f + __expf(-z));
    }
}

// ---------------------------------------------------------------------------
extern "C" void kernel_launch(void* const* d_in, const int* in_sizes, int n_in,
                              void* d_out, int out_size) {
    const float* x = (const float*)d_in[0];
    const void* ei = d_in[1];
    const float* ea = (const float*)d_in[2];

    int base = (in_sizes[3] == 128) ? 3 : 4;
    const float* W1 = (const float*)d_in[base + 0];
    const float* b1 = (const float*)d_in[base + 1];
    const float* W2 = (const float*)d_in[base + 2];
    const float* b2 = (const float*)d_in[base + 3];
    const float* mW1 = (const float*)d_in[base + 4];
    const float* mb1 = (const float*)d_in[base + 5];
    const float* mW2 = (const float*)d_in[base + 6];
    const float* mb2 = (const float*)d_in[base + 7];

    int n = in_sizes[0] / 2;
    int e = in_sizes[1] / 2;
    float* out = (float*)d_out;

    const int B = 256;
    int gn = (n + B - 1) / B;
    int ge = (e + B - 1) / B;
    int gn4 = (n + 63) / 64;
    int ge2 = (e + 127) / 128;         // 2 threads per edge

    k_init<<<gn, B>>>((const unsigned*)ei, e, n);
    k_prep<<<ge, B>>>(ei, e);
    k_scan1<<<gn, B>>>(n);
    k_scan<<<gn, B>>>(x, n);
    k_scatter<<<ge, B>>>(e);
    k_layer1<<<gn, B>>>(W1, b1, W2, n);
    k_layer2<<<gn4, B>>>(mW1, b2, n);
    k_edge<<<ge2, B>>>(ea, mW1, mb1, mW2, mb2, out, e);
}

// round 16
// speedup vs baseline: 1.1723x; 1.0036x over previous
#include <cuda_runtime.h>
#include <cuda_fp16.h>
#include <math.h>

#define NMAX 100000
#define EMAX 1600000
#define NBLK ((NMAX + 255) / 256)   // 391

// Scratch (device globals; zero-initialized at module load — g_degi relies on this
// for the first run; k_scatter re-zeroes it for every subsequent run/replay)
__device__ __align__(16) int                g_degi[NMAX];
__device__ __align__(16) int                g_start[NMAX + 1];
__device__ __align__(16) int                g_bsum[NBLK + 1];
__device__ __align__(16) int                g_srcs[EMAX];
__device__ __align__(16) unsigned long long g_edge[EMAX];  // r:17 | c:17<<17 | rank<<34
__device__ __align__(16) float              g_dinv[NMAX];
__device__ __align__(16) float              g_xn[NMAX * 2];
__device__ __align__(16) __half             g_h2n[NMAX * 32];
__device__ __align__(16) __half             g_na[NMAX * 16];
__device__ __align__(16) __half             g_nb[NMAX * 16];

// ---------------------------------------------------------------------------
// decode edge_index; histogram in-degree; pack (r, c, rank) into u64.
// dtype probe is block-local: int64 data has all-zero odd 32-bit words;
// int32 data (random indices) fails that for 256 samples with P ~ 1e-1280.
__global__ void k_prep(const void* __restrict__ ei, int e) {
    int i = blockIdx.x * blockDim.x + threadIdx.x;
    bool nz = false;
    if (i < e) {
        nz = (reinterpret_cast<const unsigned*>(ei)[2 * (size_t)i + 1] != 0u);
    }
    bool i64 = !__syncthreads_or((int)nz);
    if (i >= e) return;
    unsigned r, c;
    if (i64) {
        r = (unsigned)(reinterpret_cast<const long long*>(ei)[i]);
        c = (unsigned)(reinterpret_cast<const long long*>(ei)[(size_t)e + i]);
    } else {
        r = (unsigned)reinterpret_cast<const int*>(ei)[i];
        c = (unsigned)reinterpret_cast<const int*>(ei)[(size_t)e + i];
    }
    unsigned rank = (unsigned)atomicAdd(&g_degi[c], 1);
    g_edge[i] = (unsigned long long)r | ((unsigned long long)c << 17)
              | ((unsigned long long)rank << 34);
}

// scan phase 1: per-block sums of degi
__global__ void k_scan1(int n) {
    __shared__ int ws[8];
    int lane = threadIdx.x & 31, wid = threadIdx.x >> 5;
    int i = blockIdx.x * 256 + threadIdx.x;
    int v = (i < n) ? g_degi[i] : 0;
#pragma unroll
    for (int o = 16; o > 0; o >>= 1) v += __shfl_down_sync(0xFFFFFFFFu, v, o);
    if (lane == 0) ws[wid] = v;
    __syncthreads();
    if (threadIdx.x == 0) {
        int s = 0;
#pragma unroll
        for (int w = 0; w < 8; w++) s += ws[w];
        g_bsum[blockIdx.x] = s;
    }
}

// scan phase 2+3 fused: each block reduces bsum[0..b) for its own offset,
// then local exclusive scan; writes start, dinv, xn. Block 0 sets start[n]=e.
__global__ void k_scan(const float* __restrict__ x, int n, int e) {
    __shared__ int ws[8];
    __shared__ int s_boff;
    int t = threadIdx.x;
    int lane = t & 31, wid = t >> 5;
    int b = blockIdx.x;
    if (b == 0 && t == 0) g_start[n] = e;

    {
        int v = 0;
        if (t < b) v += g_bsum[t];
        if (t + 256 < b) v += g_bsum[t + 256];
#pragma unroll
        for (int o = 16; o > 0; o >>= 1) v += __shfl_down_sync(0xFFFFFFFFu, v, o);
        if (lane == 0) ws[wid] = v;
        __syncthreads();
        if (t == 0) {
            int s = 0;
#pragma unroll
            for (int w = 0; w < 8; w++) s += ws[w];
            s_boff = s;
        }
        __syncthreads();
    }

    int i = b * 256 + t;
    int v = (i < n) ? g_degi[i] : 0;
    int s = v;
#pragma unroll
    for (int o = 1; o < 32; o <<= 1) {
        int u = __shfl_up_sync(0xFFFFFFFFu, s, o);
        if (lane >= o) s += u;
    }
    if (lane == 31) ws[wid] = s;
    __syncthreads();
    if (wid == 0 && lane < 8) {
        int w = ws[lane];
#pragma unroll
        for (int o = 1; o < 8; o <<= 1) {
            int u = __shfl_up_sync(0x000000FFu, w, o);
            if (lane >= o) w += u;
        }
        ws[lane] = w;
    }
    __syncthreads();
    int excl = s_boff + (wid ? ws[wid - 1] : 0) + s - v;
    if (i < n) {
        g_start[i] = excl;
        float di = rsqrtf((float)(v + 1));
        g_dinv[i] = di;
        float2 xv = reinterpret_cast<const float2*>(x)[i];
        reinterpret_cast<float2*>(g_xn)[i] = make_float2(di * xv.x, di * xv.y);
    }
}

// scatter edges into CSR slots — atomic-free; also re-zero degi for next run
// (degi's last reader is k_scan; zero-init at load covers the first run).
__global__ void k_scatter(int e, int n) {
    int i = blockIdx.x * blockDim.x + threadIdx.x;
    if (i < n) g_degi[i] = 0;
    if (i >= e) return;
    unsigned long long v = g_edge[i];
    int r = (int)(v & 0x1FFFFu);
    int c = (int)((v >> 17) & 0x1FFFFu);
    int rank = (int)(v >> 34);
    g_srcs[g_start[c] + rank] = r;
}

// layer 1 fused: gather xn (unroll-4), GEMV, write fp16 h2n
__global__ void k_layer1(const float* __restrict__ W1,  // [2,64]
                         const float* __restrict__ b1,  // [64]
                         const float* __restrict__ W2,  // [64,32]
                         int n) {
    __shared__ float sW1[128];
    __shared__ float sb1[64];
    __shared__ float sW2[2048];
    int t = threadIdx.x;
    for (int i = t; i < 128; i += blockDim.x) sW1[i] = W1[i];
    for (int i = t; i < 64; i += blockDim.x) sb1[i] = b1[i];
    for (int i = t; i < 2048; i += blockDim.x) sW2[i] = W2[i];
    __syncthreads();

    int nn = blockIdx.x * blockDim.x + t;
    if (nn >= n) return;
    int s0 = g_start[nn], s1 = g_start[nn + 1];
    float a0 = 0.0f, a1 = 0.0f;
    int j = s0;
    for (; j + 4 <= s1; j += 4) {
        int r0 = g_srcs[j], r1 = g_srcs[j + 1], r2 = g_srcs[j + 2], r3 = g_srcs[j + 3];
        float2 v0 = reinterpret_cast<const float2*>(g_xn)[r0];
        float2 v1 = reinterpret_cast<const float2*>(g_xn)[r1];
        float2 v2 = reinterpret_cast<const float2*>(g_xn)[r2];
        float2 v3 = reinterpret_cast<const float2*>(g_xn)[r3];
        a0 += (v0.x + v1.x) + (v2.x + v3.x);
        a1 += (v0.y + v1.y) + (v2.y + v3.y);
    }
    for (; j < s1; j++) {
        float2 v = reinterpret_cast<const float2*>(g_xn)[g_srcs[j]];
        a0 += v.x; a1 += v.y;
    }
    float di = g_dinv[nn];
    float2 xv = reinterpret_cast<const float2*>(g_xn)[nn];
    float v0 = di * (a0 + xv.x);
    float v1 = di * (a1 + xv.y);

    float acc[32];
#pragma unroll
    for (int k = 0; k < 32; k++) acc[k] = 0.0f;
#pragma unroll 4
    for (int jj = 0; jj < 64; jj++) {
        float h = fmaxf(fmaf(v0, sW1[jj], fmaf(v1, sW1[64 + jj], sb1[jj])), 0.0f);
#pragma unroll
        for (int k = 0; k < 32; k++) acc[k] = fmaf(h, sW2[jj * 32 + k], acc[k]);
    }

    __half2 hp[16];
#pragma unroll
    for (int k = 0; k < 16; k++)
        hp[k] = __floats2half2_rn(di * acc[2 * k], di * acc[2 * k + 1]);
    uint4* o = reinterpret_cast<uint4*>(g_h2n + (size_t)nn * 32);
    const uint4* src = reinterpret_cast<const uint4*>(hp);
#pragma unroll
    for (int k = 0; k < 4; k++) o[k] = src[k];
}

__device__ __forceinline__ void acc_slice(float* acc, uint4 raw) {
    const __half2* hh = reinterpret_cast<const __half2*>(&raw);
#pragma unroll
    for (int k = 0; k < 4; k++) {
        float2 f = __half22float2(hh[k]);
        acc[2 * k] += f.x; acc[2 * k + 1] += f.y;
    }
}

// layer 2 fused, 4 threads/node, gather unroll-4 (MLP 4)
__global__ void k_layer2(const float* __restrict__ mW1,  // [65,16]
                         const float* __restrict__ b2,   // [32]
                         int n) {
    __shared__ float sAB[1024];
    __shared__ float sb2[32];
    __shared__ float sh[64 * 32];
    int t = threadIdx.x;
    for (int idx = t; idx < 1024; idx += blockDim.x) {
        int k = idx >> 5, i = idx & 31;
        sAB[idx] = (i < 16) ? mW1[k * 16 + i] : mW1[(32 + k) * 16 + (i - 16)];
    }
    for (int i = t; i < 32; i += blockDim.x) sb2[i] = b2[i];
    __syncthreads();

    int local = t >> 2;
    int p = t & 3;
    int nn = blockIdx.x * 64 + local;
    bool active = (nn < n);

    if (active) {
        int s0 = g_start[nn], s1 = g_start[nn + 1];
        float acc[8];
        {
            uint4 raw = reinterpret_cast<const uint4*>(g_h2n + (size_t)nn * 32)[p];
            const __half2* hh = reinterpret_cast<const __half2*>(&raw);
#pragma unroll
            for (int k = 0; k < 4; k++) {
                float2 f = __half22float2(hh[k]);
                acc[2 * k] = f.x; acc[2 * k + 1] = f.y;
            }
        }
        int j = s0;
        for (; j + 4 <= s1; j += 4) {
            int r0 = g_srcs[j], r1 = g_srcs[j + 1], r2 = g_srcs[j + 2], r3 = g_srcs[j + 3];
            uint4 w0 = reinterpret_cast<const uint4*>(g_h2n + (size_t)r0 * 32)[p];
            uint4 w1 = reinterpret_cast<const uint4*>(g_h2n + (size_t)r1 * 32)[p];
            uint4 w2 = reinterpret_cast<const uint4*>(g_h2n + (size_t)r2 * 32)[p];
            uint4 w3 = reinterpret_cast<const uint4*>(g_h2n + (size_t)r3 * 32)[p];
            acc_slice(acc, w0);
            acc_slice(acc, w1);
            acc_slice(acc, w2);
            acc_slice(acc, w3);
        }
        for (; j < s1; j++) {
            int r0 = g_srcs[j];
            acc_slice(acc, reinterpret_cast<const uint4*>(g_h2n + (size_t)r0 * 32)[p]);
        }
        float di = g_dinv[nn];
#pragma unroll
        for (int k = 0; k < 8; k++)
            sh[local * 32 + 8 * p + k] = fmaxf(fmaf(di, acc[k], sb2[8 * p + k]), 0.0f);
    }
    __syncthreads();

    if (active) {
        float o8[8];
#pragma unroll
        for (int i = 0; i < 8; i++) o8[i] = 0.0f;
        const float* hrow = sh + local * 32;
#pragma unroll 8
        for (int k = 0; k < 32; k++) {
            float h = hrow[k];
            const float* w = sAB + k * 32 + 8 * p;
#pragma unroll
            for (int i = 0; i < 8; i++) o8[i] = fmaf(h, w[i], o8[i]);
        }
        __half2 hp[4];
#pragma unroll
        for (int k = 0; k < 4; k++)
            hp[k] = __floats2half2_rn(o8[2 * k], o8[2 * k + 1]);
        __half* base = (p < 2) ? (g_na + (size_t)nn * 16 + 8 * p)
                               : (g_nb + (size_t)nn * 16 + 8 * (p - 2));
        *reinterpret_cast<uint4*>(base) = *reinterpret_cast<const uint4*>(hp);
    }
}

// per edge, 2 threads/edge: lane p loads 16B slice p of na[r] and nb[c]
// (pair hits the same 128B line -> half the L1tex wavefronts), computes
// 8 hidden units, shfl-combines, lane 0 writes sigmoid.
__global__ void k_edge(const float* __restrict__ ea,
                       const float* __restrict__ mW1,
                       const float* __restrict__ mb1,
                       const float* __restrict__ mW2,
                       const float* __restrict__ mb2,
                       float* __restrict__ out, int e) {
    __shared__ float sw64[16], smb1[16], smw2[16];
    __shared__ float smb2;
    int t = threadIdx.x;
    if (t < 16) {
        sw64[t] = mW1[64 * 16 + t];
        smb1[t] = mb1[t];
        smw2[t] = mW2[t];
    }
    if (t == 0) smb2 = mb2[0];
    __syncthreads();

    int i = blockIdx.x * 128 + (t >> 1);   // edge index
    int p = t & 1;                          // slice
    if (i >= e) return;
    unsigned long long v = g_edge[i];
    int r = (int)(v & 0x1FFFFu);
    int c = (int)((v >> 17) & 0x1FFFFu);
    float attr = ea[i];

    uint4 ra = reinterpret_cast<const uint4*>(g_na + (size_t)r * 16)[p];
    uint4 rb = reinterpret_cast<const uint4*>(g_nb + (size_t)c * 16)[p];
    const __half2* ha = reinterpret_cast<const __half2*>(&ra);
    const __half2* hb = reinterpret_cast<const __half2*>(&rb);

    int k0 = 8 * p;
    float s = 0.0f;
#pragma unroll
    for (int q = 0; q < 4; q++) {
        float2 av = __half22float2(ha[q]);
        float2 bv = __half22float2(hb[q]);
        float h;
        h = fmaxf(av.x + bv.x + fmaf(attr, sw64[k0 + 2 * q], smb1[k0 + 2 * q]), 0.0f);
        s = fmaf(h, smw2[k0 + 2 * q], s);
        h = fmaxf(av.y + bv.y + fmaf(attr, sw64[k0 + 2 * q + 1], smb1[k0 + 2 * q + 1]), 0.0f);
        s = fmaf(h, smw2[k0 + 2 * q + 1], s);
    }
    s += __shfl_xor_sync(0xFFFFFFFFu, s, 1);
    if (p == 0) {
        float z = s + smb2;
        out[i] = 1.0f / (1.0f + __expf(-z));
    }
}

// ---------------------------------------------------------------------------
extern "C" void kernel_launch(void* const* d_in, const int* in_sizes, int n_in,
                              void* d_out, int out_size) {
    const float* x = (const float*)d_in[0];
    const void* ei = d_in[1];
    const float* ea = (const float*)d_in[2];

    int base = (in_sizes[3] == 128) ? 3 : 4;
    const float* W1 = (const float*)d_in[base + 0];
    const float* b1 = (const float*)d_in[base + 1];
    const float* W2 = (const float*)d_in[base + 2];
    const float* b2 = (const float*)d_in[base + 3];
    const float* mW1 = (const float*)d_in[base + 4];
    const float* mb1 = (const float*)d_in[base + 5];
    const float* mW2 = (const float*)d_in[base + 6];
    const float* mb2 = (const float*)d_in[base + 7];

    int n = in_sizes[0] / 2;
    int e = in_sizes[1] / 2;
    float* out = (float*)d_out;

    const int B = 256;
    int gn = (n + B - 1) / B;
    int ge = (e + B - 1) / B;
    int gn4 = (n + 63) / 64;
    int ge2 = (e + 127) / 128;         // 2 threads per edge

    k_prep<<<ge, B>>>(ei, e);
    k_scan1<<<gn, B>>>(n);
    k_scan<<<gn, B>>>(x, n, e);
    k_scatter<<<ge, B>>>(e, n);
    k_layer1<<<gn, B>>>(W1, b1, W2, n);
    k_layer2<<<gn4, B>>>(mW1, b2, n);
    k_edge<<<ge2, B>>>(ea, mW1, mb1, mW2, mb2, out, e);
}